// round 1
// baseline (speedup 1.0000x reference)
#include <cuda_runtime.h>

// WaveletAttention: 3-level Haar DWT -> per-batch scalar gates -> gated IDWT.
// B=16, H=W=1024, fp32. Haar is local: each 8x8 input block maps to exactly
// 1 approx + 3 L3 + 12 L2 + 48 L1 coefficients, so both passes are done
// per-thread in registers with no coefficient materialization.

#define HH 1024
#define WW 1024
#define NB 16
#define N1c 262144   // per-component finest detail count (512*512), weights Wd3
#define N2c 65536    // 256*256, weights Wd2
#define N3c 16384    // 128*128, weights Wd1 (coarsest)

// logits/gates layout per batch (10 floats):
// [0]   approx (sigmoid)
// [1:4] L3 detail logits/gates (Wd1, coarsest)
// [4:7] L2 (Wd2)
// [7:10] L1 (Wd3, finest)
__device__ float g_logits[NB * 10];
__device__ float g_gates[NB * 10];

__global__ void k_zero() {
    int i = blockIdx.x * blockDim.x + threadIdx.x;
    if (i < NB * 10) g_logits[i] = 0.0f;
}

__device__ __forceinline__ void haar_fwd(float x00, float x01, float x10, float x11,
                                         float& a, float& h, float& v, float& dd) {
    float s0 = x00 + x01, m0 = x00 - x01;
    float s1 = x10 + x11, m1 = x10 - x11;
    a  = 0.5f * (s0 + s1);
    h  = 0.5f * (s0 - s1);
    v  = 0.5f * (m0 + m1);
    dd = 0.5f * (m0 - m1);
}

__device__ __forceinline__ void haar_inv(float a, float h, float v, float dd,
                                         float& x00, float& x01, float& x10, float& x11) {
    float ph = a + h, mh = a - h;
    float pv = v + dd, mv = v - dd;
    x00 = 0.5f * (ph + pv);
    x01 = 0.5f * (ph - pv);
    x10 = 0.5f * (mh + mv);
    x11 = 0.5f * (mh - mv);
}

// ---------------------------------------------------------------------------
// K1: forward DWT (recompute, registers only) + logit reductions
// grid: (64, NB), block: 256  -> one thread per 8x8 block (128x128 per batch)
// ---------------------------------------------------------------------------
__global__ void __launch_bounds__(256) k_forward(
    const float* __restrict__ x,
    const float* __restrict__ Wa,
    const float* __restrict__ Wd1,   // [3*N3c, 3] coarsest
    const float* __restrict__ Wd2,   // [3*N2c, 3]
    const float* __restrict__ Wd3)   // [3*N1c, 3] finest
{
    const int batch = blockIdx.y;
    const int bt = blockIdx.x * blockDim.x + threadIdx.x;   // 0..16383
    const int by = bt >> 7;
    const int bx = bt & 127;
    const float* xb = x + (size_t)batch * (HH * WW);
    const int y0 = by * 8, x0 = bx * 8;

    float sa = 0.0f;
    float s1[3] = {0.f, 0.f, 0.f};
    float s2[3] = {0.f, 0.f, 0.f};
    float s3[3] = {0.f, 0.f, 0.f};
    float A1[4][4];

    // ---- level 1: stream input row-pairs, accumulate L1 detail dots ----
    #pragma unroll
    for (int ry = 0; ry < 4; ry++) {
        const float* row0 = xb + (size_t)(y0 + 2 * ry) * WW + x0;
        const float* row1 = row0 + WW;
        float4 p0 = *(const float4*)(row0);
        float4 p1 = *(const float4*)(row0 + 4);
        float4 q0 = *(const float4*)(row1);
        float4 q1 = *(const float4*)(row1 + 4);
        float r0[8] = {p0.x, p0.y, p0.z, p0.w, p1.x, p1.y, p1.z, p1.w};
        float r1[8] = {q0.x, q0.y, q0.z, q0.w, q1.x, q1.y, q1.z, q1.w};
        int y1 = by * 4 + ry;
        #pragma unroll
        for (int c = 0; c < 4; c++) {
            float a, h, v, dd;
            haar_fwd(r0[2*c], r0[2*c+1], r1[2*c], r1[2*c+1], a, h, v, dd);
            A1[ry][c] = a;
            int i = y1 * 512 + bx * 4 + c;
            const float* wh = Wd3 + 3 * (size_t)i;
            const float* wv = Wd3 + 3 * (size_t)(N1c + i);
            const float* wd = Wd3 + 3 * (size_t)(2 * N1c + i);
            #pragma unroll
            for (int j = 0; j < 3; j++)
                s1[j] += h * __ldg(wh + j) + v * __ldg(wv + j) + dd * __ldg(wd + j);
        }
    }

    // ---- level 2 ----
    float A2[2][2];
    #pragma unroll
    for (int ry = 0; ry < 2; ry++) {
        #pragma unroll
        for (int c = 0; c < 2; c++) {
            float a, h, v, dd;
            haar_fwd(A1[2*ry][2*c], A1[2*ry][2*c+1], A1[2*ry+1][2*c], A1[2*ry+1][2*c+1],
                     a, h, v, dd);
            A2[ry][c] = a;
            int i = (by * 2 + ry) * 256 + bx * 2 + c;
            const float* wh = Wd2 + 3 * (size_t)i;
            const float* wv = Wd2 + 3 * (size_t)(N2c + i);
            const float* wd = Wd2 + 3 * (size_t)(2 * N2c + i);
            #pragma unroll
            for (int j = 0; j < 3; j++)
                s2[j] += h * __ldg(wh + j) + v * __ldg(wv + j) + dd * __ldg(wd + j);
        }
    }

    // ---- level 3 ----
    {
        float a, h, v, dd;
        haar_fwd(A2[0][0], A2[0][1], A2[1][0], A2[1][1], a, h, v, dd);
        int i = by * 128 + bx;
        const float* wh = Wd1 + 3 * (size_t)i;
        const float* wv = Wd1 + 3 * (size_t)(N3c + i);
        const float* wd = Wd1 + 3 * (size_t)(2 * N3c + i);
        #pragma unroll
        for (int j = 0; j < 3; j++)
            s3[j] += h * __ldg(wh + j) + v * __ldg(wv + j) + dd * __ldg(wd + j);
        sa = a * __ldg(Wa + i);
    }

    // ---- block reduction of 10 scalars ----
    float vals[10] = {sa, s3[0], s3[1], s3[2], s2[0], s2[1], s2[2], s1[0], s1[1], s1[2]};
    __shared__ float sm[10][8];
    int lane = threadIdx.x & 31;
    int wid  = threadIdx.x >> 5;
    #pragma unroll
    for (int k = 0; k < 10; k++) {
        float v = vals[k];
        #pragma unroll
        for (int off = 16; off > 0; off >>= 1)
            v += __shfl_down_sync(0xFFFFFFFFu, v, off);
        if (lane == 0) sm[k][wid] = v;
    }
    __syncthreads();
    if (threadIdx.x < 10) {
        float t = 0.f;
        #pragma unroll
        for (int w = 0; w < 8; w++) t += sm[threadIdx.x][w];
        atomicAdd(&g_logits[batch * 10 + threadIdx.x], t);
    }
}

// ---------------------------------------------------------------------------
// K2: per-batch gates (tiny)
// ---------------------------------------------------------------------------
__device__ __forceinline__ void softmax3(const float* l, const float* bd, float* g) {
    float l0 = l[0] + bd[0], l1 = l[1] + bd[1], l2 = l[2] + bd[2];
    float m = fmaxf(fmaxf(l0, l1), l2);
    float e0 = __expf(l0 - m), e1 = __expf(l1 - m), e2 = __expf(l2 - m);
    float inv = 1.0f / (e0 + e1 + e2);
    g[0] = e0 * inv; g[1] = e1 * inv; g[2] = e2 * inv;
}

__global__ void k_gates(const float* __restrict__ ba,
                        const float* __restrict__ bd1,
                        const float* __restrict__ bd2,
                        const float* __restrict__ bd3)
{
    int b = threadIdx.x;
    if (b >= NB) return;
    const float* L = g_logits + b * 10;
    float* G = g_gates + b * 10;
    G[0] = 1.0f / (1.0f + __expf(-(L[0] + ba[0])));
    softmax3(L + 1, bd1, G + 1);
    softmax3(L + 4, bd2, G + 4);
    softmax3(L + 7, bd3, G + 7);
}

// ---------------------------------------------------------------------------
// K3: recompute forward DWT, gate, inverse 3 levels, write 8x8 output
// ---------------------------------------------------------------------------
__global__ void __launch_bounds__(256) k_recon(
    const float* __restrict__ x, float* __restrict__ out)
{
    const int batch = blockIdx.y;
    const int bt = blockIdx.x * blockDim.x + threadIdx.x;
    const int by = bt >> 7;
    const int bx = bt & 127;
    const float* xb = x + (size_t)batch * (HH * WW);
    float* ob = out + (size_t)batch * (HH * WW);
    const int y0 = by * 8, x0 = bx * 8;

    const float* G = g_gates + batch * 10;
    const float aw  = G[0];
    const float g3h = G[1], g3v = G[2], g3d = G[3];
    const float g2h = G[4], g2v = G[5], g2d = G[6];
    const float g1h = G[7], g1v = G[8], g1d = G[9];

    float A1[4][4], H1[4][4], V1[4][4], D1[4][4];

    // forward level 1, gating L1 details immediately
    #pragma unroll
    for (int ry = 0; ry < 4; ry++) {
        const float* row0 = xb + (size_t)(y0 + 2 * ry) * WW + x0;
        const float* row1 = row0 + WW;
        float4 p0 = *(const float4*)(row0);
        float4 p1 = *(const float4*)(row0 + 4);
        float4 q0 = *(const float4*)(row1);
        float4 q1 = *(const float4*)(row1 + 4);
        float r0[8] = {p0.x, p0.y, p0.z, p0.w, p1.x, p1.y, p1.z, p1.w};
        float r1[8] = {q0.x, q0.y, q0.z, q0.w, q1.x, q1.y, q1.z, q1.w};
        #pragma unroll
        for (int c = 0; c < 4; c++) {
            float a, h, v, dd;
            haar_fwd(r0[2*c], r0[2*c+1], r1[2*c], r1[2*c+1], a, h, v, dd);
            A1[ry][c] = a;
            H1[ry][c] = h * g1h;
            V1[ry][c] = v * g1v;
            D1[ry][c] = dd * g1d;
        }
    }

    // forward level 2, gated
    float A2[2][2], H2[2][2], V2[2][2], D2[2][2];
    #pragma unroll
    for (int ry = 0; ry < 2; ry++) {
        #pragma unroll
        for (int c = 0; c < 2; c++) {
            float a, h, v, dd;
            haar_fwd(A1[2*ry][2*c], A1[2*ry][2*c+1], A1[2*ry+1][2*c], A1[2*ry+1][2*c+1],
                     a, h, v, dd);
            A2[ry][c] = a;
            H2[ry][c] = h * g2h;
            V2[ry][c] = v * g2v;
            D2[ry][c] = dd * g2d;
        }
    }

    // forward level 3, gate, inverse level 3
    float R2[2][2];
    {
        float a, h, v, dd;
        haar_fwd(A2[0][0], A2[0][1], A2[1][0], A2[1][1], a, h, v, dd);
        a *= aw; h *= g3h; v *= g3v; dd *= g3d;
        haar_inv(a, h, v, dd, R2[0][0], R2[0][1], R2[1][0], R2[1][1]);
    }

    // inverse level 2
    float R1[4][4];
    #pragma unroll
    for (int ry = 0; ry < 2; ry++) {
        #pragma unroll
        for (int c = 0; c < 2; c++) {
            haar_inv(R2[ry][c], H2[ry][c], V2[ry][c], D2[ry][c],
                     R1[2*ry][2*c], R1[2*ry][2*c+1], R1[2*ry+1][2*c], R1[2*ry+1][2*c+1]);
        }
    }

    // inverse level 1 + store (row-pair at a time, float4 stores)
    #pragma unroll
    for (int ry = 0; ry < 4; ry++) {
        float o0[8], o1[8];
        #pragma unroll
        for (int c = 0; c < 4; c++) {
            haar_inv(R1[ry][c], H1[ry][c], V1[ry][c], D1[ry][c],
                     o0[2*c], o0[2*c+1], o1[2*c], o1[2*c+1]);
        }
        float* w0 = ob + (size_t)(y0 + 2 * ry) * WW + x0;
        float* w1 = w0 + WW;
        *(float4*)(w0)     = make_float4(o0[0], o0[1], o0[2], o0[3]);
        *(float4*)(w0 + 4) = make_float4(o0[4], o0[5], o0[6], o0[7]);
        *(float4*)(w1)     = make_float4(o1[0], o1[1], o1[2], o1[3]);
        *(float4*)(w1 + 4) = make_float4(o1[4], o1[5], o1[6], o1[7]);
    }
}

// ---------------------------------------------------------------------------
extern "C" void kernel_launch(void* const* d_in, const int* in_sizes, int n_in,
                              void* d_out, int out_size) {
    const float* x   = (const float*)d_in[0];
    const float* Wa  = (const float*)d_in[1];
    const float* ba  = (const float*)d_in[2];
    const float* Wd1 = (const float*)d_in[3];
    const float* bd1 = (const float*)d_in[4];
    const float* Wd2 = (const float*)d_in[5];
    const float* bd2 = (const float*)d_in[6];
    const float* Wd3 = (const float*)d_in[7];
    const float* bd3 = (const float*)d_in[8];
    float* out = (float*)d_out;

    k_zero<<<1, 256>>>();
    k_forward<<<dim3(64, NB), 256>>>(x, Wa, Wd1, Wd2, Wd3);
    k_gates<<<1, 32>>>(ba, bd1, bd2, bd3);
    k_recon<<<dim3(64, NB), 256>>>(x, out);
}

// round 2
// speedup vs baseline: 1.1319x; 1.1319x over previous
#include <cuda_runtime.h>

// WaveletAttention: 3-level Haar DWT -> per-batch scalar gates -> gated IDWT.
// R2: (a) vectorized weight loads in k_forward (float4/float2) to fix
//     LSU-issue bound; (b) two-pass k_recon (recompute level-1 details from
//     an L1-resident re-read of x) to cut regs 80 -> ~56 and raise occupancy.

#define HH 1024
#define WW 1024
#define NB 16
#define N1c 262144   // 512*512 per component, weights Wd3 (finest)
#define N2c 65536    // 256*256, weights Wd2
#define N3c 16384    // 128*128, weights Wd1 (coarsest)

// per batch (10 floats): [0] approx sigmoid, [1:4] L3 (Wd1), [4:7] L2 (Wd2), [7:10] L1 (Wd3)
__device__ float g_logits[NB * 10];
__device__ float g_gates[NB * 10];

__global__ void k_zero() {
    int i = blockIdx.x * blockDim.x + threadIdx.x;
    if (i < NB * 10) g_logits[i] = 0.0f;
}

__device__ __forceinline__ void haar_fwd(float x00, float x01, float x10, float x11,
                                         float& a, float& h, float& v, float& dd) {
    float s0 = x00 + x01, m0 = x00 - x01;
    float s1 = x10 + x11, m1 = x10 - x11;
    a  = 0.5f * (s0 + s1);
    h  = 0.5f * (s0 - s1);
    v  = 0.5f * (m0 + m1);
    dd = 0.5f * (m0 - m1);
}

__device__ __forceinline__ void haar_inv(float a, float h, float v, float dd,
                                         float& x00, float& x01, float& x10, float& x11) {
    float ph = a + h, mh = a - h;
    float pv = v + dd, mv = v - dd;
    x00 = 0.5f * (ph + pv);
    x01 = 0.5f * (ph - pv);
    x10 = 0.5f * (mh + mv);
    x11 = 0.5f * (mh - mv);
}

// ---------------------------------------------------------------------------
// K1: forward DWT (registers only) + logit reductions.
// One thread per 8x8 block. Weight rows for 4 consecutive coefficients are
// 12 contiguous floats (48B, 16B-aligned) -> 3 float4 loads per component.
// ---------------------------------------------------------------------------
__global__ void __launch_bounds__(256, 4) k_forward(
    const float* __restrict__ x,
    const float* __restrict__ Wa,
    const float* __restrict__ Wd1,   // [3*N3c, 3] coarsest
    const float* __restrict__ Wd2,   // [3*N2c, 3]
    const float* __restrict__ Wd3)   // [3*N1c, 3] finest
{
    const int batch = blockIdx.y;
    const int bt = blockIdx.x * blockDim.x + threadIdx.x;   // 0..16383
    const int by = bt >> 7;
    const int bx = bt & 127;
    const float* xb = x + (size_t)batch * (HH * WW);
    const int y0 = by * 8, x0 = bx * 8;

    float sa = 0.0f;
    float s1x = 0.f, s1y = 0.f, s1z = 0.f;
    float s2x = 0.f, s2y = 0.f, s2z = 0.f;
    float s3x = 0.f, s3y = 0.f, s3z = 0.f;
    float A1[4][4];

    // ---- level 1 ----
    #pragma unroll
    for (int ry = 0; ry < 4; ry++) {
        const float* row0 = xb + (size_t)(y0 + 2 * ry) * WW + x0;
        const float* row1 = row0 + WW;
        float4 p0 = *(const float4*)(row0);
        float4 p1 = *(const float4*)(row0 + 4);
        float4 q0 = *(const float4*)(row1);
        float4 q1 = *(const float4*)(row1 + 4);
        float r0[8] = {p0.x, p0.y, p0.z, p0.w, p1.x, p1.y, p1.z, p1.w};
        float r1[8] = {q0.x, q0.y, q0.z, q0.w, q1.x, q1.y, q1.z, q1.w};

        float h[4], v[4], d[4];
        #pragma unroll
        for (int c = 0; c < 4; c++) {
            float a;
            haar_fwd(r0[2*c], r0[2*c+1], r1[2*c], r1[2*c+1], a, h[c], v[c], d[c]);
            A1[ry][c] = a;
        }

        const size_t i0 = (size_t)(by * 4 + ry) * 512 + bx * 4;   // multiple of 4
        const float4* WH = (const float4*)(Wd3 + 3 * i0);
        const float4* WV = (const float4*)(Wd3 + 3 * (N1c + i0));
        const float4* WD = (const float4*)(Wd3 + 3 * (2 * (size_t)N1c + i0));
        float4 h0 = WH[0], h1 = WH[1], h2 = WH[2];
        float4 v0 = WV[0], v1 = WV[1], v2 = WV[2];
        float4 d0 = WD[0], d1 = WD[1], d2 = WD[2];
        float fh[12] = {h0.x,h0.y,h0.z,h0.w, h1.x,h1.y,h1.z,h1.w, h2.x,h2.y,h2.z,h2.w};
        float fv[12] = {v0.x,v0.y,v0.z,v0.w, v1.x,v1.y,v1.z,v1.w, v2.x,v2.y,v2.z,v2.w};
        float fd[12] = {d0.x,d0.y,d0.z,d0.w, d1.x,d1.y,d1.z,d1.w, d2.x,d2.y,d2.z,d2.w};
        #pragma unroll
        for (int c = 0; c < 4; c++) {
            s1x += h[c]*fh[3*c+0] + v[c]*fv[3*c+0] + d[c]*fd[3*c+0];
            s1y += h[c]*fh[3*c+1] + v[c]*fv[3*c+1] + d[c]*fd[3*c+1];
            s1z += h[c]*fh[3*c+2] + v[c]*fv[3*c+2] + d[c]*fd[3*c+2];
        }
    }

    // ---- level 2 ----
    float A2[2][2];
    #pragma unroll
    for (int ry = 0; ry < 2; ry++) {
        float h[2], v[2], d[2];
        #pragma unroll
        for (int c = 0; c < 2; c++) {
            float a;
            haar_fwd(A1[2*ry][2*c], A1[2*ry][2*c+1], A1[2*ry+1][2*c], A1[2*ry+1][2*c+1],
                     a, h[c], v[c], d[c]);
            A2[ry][c] = a;
        }
        const size_t i0 = (size_t)(by * 2 + ry) * 256 + bx * 2;   // multiple of 2
        const float2* WH = (const float2*)(Wd2 + 3 * i0);
        const float2* WV = (const float2*)(Wd2 + 3 * (N2c + i0));
        const float2* WD = (const float2*)(Wd2 + 3 * (2 * (size_t)N2c + i0));
        float2 a0 = WH[0], a1 = WH[1], a2 = WH[2];
        float2 b0 = WV[0], b1 = WV[1], b2 = WV[2];
        float2 c0 = WD[0], c1 = WD[1], c2 = WD[2];
        float fh[6] = {a0.x,a0.y, a1.x,a1.y, a2.x,a2.y};
        float fv[6] = {b0.x,b0.y, b1.x,b1.y, b2.x,b2.y};
        float fd[6] = {c0.x,c0.y, c1.x,c1.y, c2.x,c2.y};
        #pragma unroll
        for (int c = 0; c < 2; c++) {
            s2x += h[c]*fh[3*c+0] + v[c]*fv[3*c+0] + d[c]*fd[3*c+0];
            s2y += h[c]*fh[3*c+1] + v[c]*fv[3*c+1] + d[c]*fd[3*c+1];
            s2z += h[c]*fh[3*c+2] + v[c]*fv[3*c+2] + d[c]*fd[3*c+2];
        }
    }

    // ---- level 3 ----
    {
        float a, h, v, dd;
        haar_fwd(A2[0][0], A2[0][1], A2[1][0], A2[1][1], a, h, v, dd);
        const size_t i = (size_t)by * 128 + bx;
        const float* wh = Wd1 + 3 * i;
        const float* wv = Wd1 + 3 * (N3c + i);
        const float* wd = Wd1 + 3 * (2 * (size_t)N3c + i);
        s3x += h * __ldg(wh + 0) + v * __ldg(wv + 0) + dd * __ldg(wd + 0);
        s3y += h * __ldg(wh + 1) + v * __ldg(wv + 1) + dd * __ldg(wd + 1);
        s3z += h * __ldg(wh + 2) + v * __ldg(wv + 2) + dd * __ldg(wd + 2);
        sa = a * __ldg(Wa + i);
    }

    // ---- block reduction of 10 scalars ----
    float vals[10] = {sa, s3x, s3y, s3z, s2x, s2y, s2z, s1x, s1y, s1z};
    __shared__ float sm[10][8];
    int lane = threadIdx.x & 31;
    int wid  = threadIdx.x >> 5;
    #pragma unroll
    for (int k = 0; k < 10; k++) {
        float v = vals[k];
        #pragma unroll
        for (int off = 16; off > 0; off >>= 1)
            v += __shfl_down_sync(0xFFFFFFFFu, v, off);
        if (lane == 0) sm[k][wid] = v;
    }
    __syncthreads();
    if (threadIdx.x < 10) {
        float t = 0.f;
        #pragma unroll
        for (int w = 0; w < 8; w++) t += sm[threadIdx.x][w];
        atomicAdd(&g_logits[batch * 10 + threadIdx.x], t);
    }
}

// ---------------------------------------------------------------------------
// K2: per-batch gates (tiny)
// ---------------------------------------------------------------------------
__device__ __forceinline__ void softmax3(const float* l, const float* bd, float* g) {
    float l0 = l[0] + bd[0], l1 = l[1] + bd[1], l2 = l[2] + bd[2];
    float m = fmaxf(fmaxf(l0, l1), l2);
    float e0 = __expf(l0 - m), e1 = __expf(l1 - m), e2 = __expf(l2 - m);
    float inv = 1.0f / (e0 + e1 + e2);
    g[0] = e0 * inv; g[1] = e1 * inv; g[2] = e2 * inv;
}

__global__ void k_gates(const float* __restrict__ ba,
                        const float* __restrict__ bd1,
                        const float* __restrict__ bd2,
                        const float* __restrict__ bd3)
{
    int b = threadIdx.x;
    if (b >= NB) return;
    const float* L = g_logits + b * 10;
    float* G = g_gates + b * 10;
    G[0] = 1.0f / (1.0f + __expf(-(L[0] + ba[0])));
    softmax3(L + 1, bd1, G + 1);
    softmax3(L + 4, bd2, G + 4);
    softmax3(L + 7, bd3, G + 7);
}

// ---------------------------------------------------------------------------
// K3: two-pass reconstruct. Pass A: approx path only (A1->A2->L3 gate ->
// invert -> R1). Pass B: re-read x (L1/L2 hot), recompute level-1 details,
// gate, invert, store. Keeps live set ~R1[16]+rows[16] -> higher occupancy.
// ---------------------------------------------------------------------------
__global__ void __launch_bounds__(256, 4) k_recon(
    const float* __restrict__ x, float* __restrict__ out)
{
    const int batch = blockIdx.y;
    const int bt = blockIdx.x * blockDim.x + threadIdx.x;
    const int by = bt >> 7;
    const int bx = bt & 127;
    const float* xb = x + (size_t)batch * (HH * WW);
    float* ob = out + (size_t)batch * (HH * WW);
    const int y0 = by * 8, x0 = bx * 8;

    const float* G = g_gates + batch * 10;
    const float aw  = __ldg(G + 0);
    const float g3h = __ldg(G + 1), g3v = __ldg(G + 2), g3d = __ldg(G + 3);
    const float g2h = __ldg(G + 4), g2v = __ldg(G + 5), g2d = __ldg(G + 6);
    const float g1h = __ldg(G + 7), g1v = __ldg(G + 8), g1d = __ldg(G + 9);

    // ---- pass A: approx chain only ----
    float A1[4][4];
    #pragma unroll
    for (int ry = 0; ry < 4; ry++) {
        const float* row0 = xb + (size_t)(y0 + 2 * ry) * WW + x0;
        const float* row1 = row0 + WW;
        float4 p0 = *(const float4*)(row0);
        float4 p1 = *(const float4*)(row0 + 4);
        float4 q0 = *(const float4*)(row1);
        float4 q1 = *(const float4*)(row1 + 4);
        A1[ry][0] = 0.5f * ((p0.x + p0.y) + (q0.x + q0.y));
        A1[ry][1] = 0.5f * ((p0.z + p0.w) + (q0.z + q0.w));
        A1[ry][2] = 0.5f * ((p1.x + p1.y) + (q1.x + q1.y));
        A1[ry][3] = 0.5f * ((p1.z + p1.w) + (q1.z + q1.w));
    }

    float A2[2][2], H2[2][2], V2[2][2], D2[2][2];
    #pragma unroll
    for (int ry = 0; ry < 2; ry++) {
        #pragma unroll
        for (int c = 0; c < 2; c++) {
            float a, h, v, dd;
            haar_fwd(A1[2*ry][2*c], A1[2*ry][2*c+1], A1[2*ry+1][2*c], A1[2*ry+1][2*c+1],
                     a, h, v, dd);
            A2[ry][c] = a;
            H2[ry][c] = h * g2h;
            V2[ry][c] = v * g2v;
            D2[ry][c] = dd * g2d;
        }
    }

    float R2[2][2];
    {
        float a, h, v, dd;
        haar_fwd(A2[0][0], A2[0][1], A2[1][0], A2[1][1], a, h, v, dd);
        a *= aw; h *= g3h; v *= g3v; dd *= g3d;
        haar_inv(a, h, v, dd, R2[0][0], R2[0][1], R2[1][0], R2[1][1]);
    }

    float R1[4][4];
    #pragma unroll
    for (int ry = 0; ry < 2; ry++) {
        #pragma unroll
        for (int c = 0; c < 2; c++) {
            haar_inv(R2[ry][c], H2[ry][c], V2[ry][c], D2[ry][c],
                     R1[2*ry][2*c], R1[2*ry][2*c+1], R1[2*ry+1][2*c], R1[2*ry+1][2*c+1]);
        }
    }

    // ---- pass B: re-read x (cache-hot), recompute L1 details, invert, store ----
    #pragma unroll
    for (int ry = 0; ry < 4; ry++) {
        const float* row0 = xb + (size_t)(y0 + 2 * ry) * WW + x0;
        const float* row1 = row0 + WW;
        float4 p0 = *(const float4*)(row0);
        float4 p1 = *(const float4*)(row0 + 4);
        float4 q0 = *(const float4*)(row1);
        float4 q1 = *(const float4*)(row1 + 4);
        float r0[8] = {p0.x, p0.y, p0.z, p0.w, p1.x, p1.y, p1.z, p1.w};
        float r1[8] = {q0.x, q0.y, q0.z, q0.w, q1.x, q1.y, q1.z, q1.w};
        float o0[8], o1[8];
        #pragma unroll
        for (int c = 0; c < 4; c++) {
            float a, h, v, dd;
            haar_fwd(r0[2*c], r0[2*c+1], r1[2*c], r1[2*c+1], a, h, v, dd);
            haar_inv(R1[ry][c], h * g1h, v * g1v, dd * g1d,
                     o0[2*c], o0[2*c+1], o1[2*c], o1[2*c+1]);
        }
        float* w0 = ob + (size_t)(y0 + 2 * ry) * WW + x0;
        float* w1 = w0 + WW;
        *(float4*)(w0)     = make_float4(o0[0], o0[1], o0[2], o0[3]);
        *(float4*)(w0 + 4) = make_float4(o0[4], o0[5], o0[6], o0[7]);
        *(float4*)(w1)     = make_float4(o1[0], o1[1], o1[2], o1[3]);
        *(float4*)(w1 + 4) = make_float4(o1[4], o1[5], o1[6], o1[7]);
    }
}

// ---------------------------------------------------------------------------
extern "C" void kernel_launch(void* const* d_in, const int* in_sizes, int n_in,
                              void* d_out, int out_size) {
    const float* x   = (const float*)d_in[0];
    const float* Wa  = (const float*)d_in[1];
    const float* ba  = (const float*)d_in[2];
    const float* Wd1 = (const float*)d_in[3];
    const float* bd1 = (const float*)d_in[4];
    const float* Wd2 = (const float*)d_in[5];
    const float* bd2 = (const float*)d_in[6];
    const float* Wd3 = (const float*)d_in[7];
    const float* bd3 = (const float*)d_in[8];
    float* out = (float*)d_out;

    k_zero<<<1, 256>>>();
    k_forward<<<dim3(64, NB), 256>>>(x, Wa, Wd1, Wd2, Wd3);
    k_gates<<<1, 32>>>(ba, bd1, bd2, bd3);
    k_recon<<<dim3(64, NB), 256>>>(x, out);
}

// round 3
// speedup vs baseline: 1.4387x; 1.2710x over previous
#include <cuda_runtime.h>

// WaveletAttention: 3-level Haar DWT -> per-batch scalar gates -> gated IDWT.
// R3: coalesced decomposition. One thread = 4 cols x 8 rows; warp = 128
// contiguous cols -> every x load / out store is a fully coalesced 512B warp
// transaction (4 L1 wavefronts/instr vs 32 before). Levels 1-2 are in-thread;
// level 3 via a single symmetric shfl_xor(1). k_recon is single-pass again.

#define HH 1024
#define WW 1024
#define NB 16
#define N1c 262144   // 512*512 per component, weights Wd3 (finest)
#define N2c 65536    // 256*256, weights Wd2
#define N3c 16384    // 128*128, weights Wd1 (coarsest)

// per batch (10): [0] approx sigmoid, [1:4] L3 (Wd1), [4:7] L2 (Wd2), [7:10] L1 (Wd3)
__device__ float g_logits[NB * 10];
__device__ float g_gates[NB * 10];

__global__ void k_zero() {
    int i = blockIdx.x * blockDim.x + threadIdx.x;
    if (i < NB * 10) g_logits[i] = 0.0f;
}

__device__ __forceinline__ void haar_fwd(float x00, float x01, float x10, float x11,
                                         float& a, float& h, float& v, float& dd) {
    float s0 = x00 + x01, m0 = x00 - x01;
    float s1 = x10 + x11, m1 = x10 - x11;
    a  = 0.5f * (s0 + s1);
    h  = 0.5f * (s0 - s1);
    v  = 0.5f * (m0 + m1);
    dd = 0.5f * (m0 - m1);
}

__device__ __forceinline__ void haar_inv(float a, float h, float v, float dd,
                                         float& x00, float& x01, float& x10, float& x11) {
    float ph = a + h, mh = a - h;
    float pv = v + dd, mv = v - dd;
    x00 = 0.5f * (ph + pv);
    x01 = 0.5f * (ph - pv);
    x10 = 0.5f * (mh + mv);
    x11 = 0.5f * (mh - mv);
}

// ---------------------------------------------------------------------------
// K1: forward DWT + logit reductions. Thread = col-group g (4 cols) x 8 rows.
// Per batch: 256 col-groups x 128 row-groups = 32768 threads (128 blocks).
// ---------------------------------------------------------------------------
__global__ void __launch_bounds__(256) k_forward(
    const float* __restrict__ x,
    const float* __restrict__ Wa,
    const float* __restrict__ Wd1,   // [3*N3c, 3] coarsest
    const float* __restrict__ Wd2,   // [3*N2c, 3]
    const float* __restrict__ Wd3)   // [3*N1c, 3] finest
{
    const int batch = blockIdx.y;
    const int bt = blockIdx.x * blockDim.x + threadIdx.x;   // 0..32767
    const int g = bt & 255;        // col group (4 cols), consecutive across lanes
    const int r = bt >> 8;         // row group (8 rows)
    const float* xb = x + (size_t)batch * (HH * WW) + (size_t)(r * 8) * WW + g * 4;

    float sa = 0.0f;
    float s1x = 0.f, s1y = 0.f, s1z = 0.f;
    float s2x = 0.f, s2y = 0.f, s2z = 0.f;
    float s3x = 0.f, s3y = 0.f, s3z = 0.f;

    float a1_0[4], a1_1[4];   // level-1 approx for col pairs 0,1 (4 rows)

    // ---- level 1: two col-pairs per thread, coalesced float4 row loads ----
    #pragma unroll
    for (int ry = 0; ry < 4; ry++) {
        float4 u = *(const float4*)(xb + (size_t)(2 * ry) * WW);
        float4 w = *(const float4*)(xb + (size_t)(2 * ry + 1) * WW);
        float h0, v0, d0, h1, v1, d1;
        haar_fwd(u.x, u.y, w.x, w.y, a1_0[ry], h0, v0, d0);
        haar_fwd(u.z, u.w, w.z, w.w, a1_1[ry], h1, v1, d1);

        const size_t i = (size_t)(r * 4 + ry) * 512 + 2 * g;   // even
        const float* ph = Wd3 + 3 * i;
        const float* pv = Wd3 + 3 * (N1c + i);
        const float* pd = Wd3 + 3 * (2 * (size_t)N1c + i);
        float2 ha = *(const float2*)(ph),     hb = *(const float2*)(ph + 2), hc = *(const float2*)(ph + 4);
        float2 va = *(const float2*)(pv),     vb = *(const float2*)(pv + 2), vc = *(const float2*)(pv + 4);
        float2 da = *(const float2*)(pd),     db = *(const float2*)(pd + 2), dc = *(const float2*)(pd + 4);
        // row i: (ha.x,ha.y,hb.x) ; row i+1: (hb.y,hc.x,hc.y)
        s1x += h0 * ha.x + h1 * hb.y + v0 * va.x + v1 * vb.y + d0 * da.x + d1 * db.y;
        s1y += h0 * ha.y + h1 * hc.x + v0 * va.y + v1 * vc.x + d0 * da.y + d1 * dc.x;
        s1z += h0 * hb.x + h1 * hc.y + v0 * vb.x + v1 * vc.y + d0 * db.x + d1 * dc.y;
    }

    // ---- level 2: one L2 column per thread, 2 rows ----
    float a2[2];
    #pragma unroll
    for (int ry2 = 0; ry2 < 2; ry2++) {
        float h, v, dd;
        haar_fwd(a1_0[2*ry2], a1_1[2*ry2], a1_0[2*ry2+1], a1_1[2*ry2+1],
                 a2[ry2], h, v, dd);
        const size_t i = (size_t)(r * 2 + ry2) * 256 + g;
        const float* ph = Wd2 + 3 * i;
        const float* pv = Wd2 + 3 * (N2c + i);
        const float* pd = Wd2 + 3 * (2 * (size_t)N2c + i);
        s2x += h * __ldg(ph + 0) + v * __ldg(pv + 0) + dd * __ldg(pd + 0);
        s2y += h * __ldg(ph + 1) + v * __ldg(pv + 1) + dd * __ldg(pd + 1);
        s2z += h * __ldg(ph + 2) + v * __ldg(pv + 2) + dd * __ldg(pd + 2);
    }

    // ---- level 3: combine lane pairs; only even lane accumulates ----
    {
        float pa0 = __shfl_xor_sync(0xFFFFFFFFu, a2[0], 1);
        float pa1 = __shfl_xor_sync(0xFFFFFFFFu, a2[1], 1);
        if ((g & 1) == 0) {
            float a, h, v, dd;
            haar_fwd(a2[0], pa0, a2[1], pa1, a, h, v, dd);
            const size_t i = (size_t)r * 128 + (g >> 1);
            const float* ph = Wd1 + 3 * i;
            const float* pv = Wd1 + 3 * (N3c + i);
            const float* pd = Wd1 + 3 * (2 * (size_t)N3c + i);
            s3x = h * __ldg(ph + 0) + v * __ldg(pv + 0) + dd * __ldg(pd + 0);
            s3y = h * __ldg(ph + 1) + v * __ldg(pv + 1) + dd * __ldg(pd + 1);
            s3z = h * __ldg(ph + 2) + v * __ldg(pv + 2) + dd * __ldg(pd + 2);
            sa  = a * __ldg(Wa + i);
        }
    }

    // ---- block reduction of 10 scalars ----
    float vals[10] = {sa, s3x, s3y, s3z, s2x, s2y, s2z, s1x, s1y, s1z};
    __shared__ float sm[10][8];
    int lane = threadIdx.x & 31;
    int wid  = threadIdx.x >> 5;
    #pragma unroll
    for (int k = 0; k < 10; k++) {
        float v = vals[k];
        #pragma unroll
        for (int off = 16; off > 0; off >>= 1)
            v += __shfl_down_sync(0xFFFFFFFFu, v, off);
        if (lane == 0) sm[k][wid] = v;
    }
    __syncthreads();
    if (threadIdx.x < 10) {
        float t = 0.f;
        #pragma unroll
        for (int w = 0; w < 8; w++) t += sm[threadIdx.x][w];
        atomicAdd(&g_logits[batch * 10 + threadIdx.x], t);
    }
}

// ---------------------------------------------------------------------------
// K2: per-batch gates (tiny)
// ---------------------------------------------------------------------------
__device__ __forceinline__ void softmax3(const float* l, const float* bd, float* g) {
    float l0 = l[0] + bd[0], l1 = l[1] + bd[1], l2 = l[2] + bd[2];
    float m = fmaxf(fmaxf(l0, l1), l2);
    float e0 = __expf(l0 - m), e1 = __expf(l1 - m), e2 = __expf(l2 - m);
    float inv = 1.0f / (e0 + e1 + e2);
    g[0] = e0 * inv; g[1] = e1 * inv; g[2] = e2 * inv;
}

__global__ void k_gates(const float* __restrict__ ba,
                        const float* __restrict__ bd1,
                        const float* __restrict__ bd2,
                        const float* __restrict__ bd3)
{
    int b = threadIdx.x;
    if (b >= NB) return;
    const float* L = g_logits + b * 10;
    float* G = g_gates + b * 10;
    G[0] = 1.0f / (1.0f + __expf(-(L[0] + ba[0])));
    softmax3(L + 1, bd1, G + 1);
    softmax3(L + 4, bd2, G + 4);
    softmax3(L + 7, bd3, G + 7);
}

// ---------------------------------------------------------------------------
// K3: single-pass reconstruct, same decomposition. Gated L1 details held in
// registers; level-3 computed symmetrically in both lanes of a pair so the
// inverse needs no redistribution shuffle.
// ---------------------------------------------------------------------------
__global__ void __launch_bounds__(256) k_recon(
    const float* __restrict__ x, float* __restrict__ out)
{
    const int batch = blockIdx.y;
    const int bt = blockIdx.x * blockDim.x + threadIdx.x;
    const int g = bt & 255;
    const int r = bt >> 8;
    const size_t base = (size_t)batch * (HH * WW) + (size_t)(r * 8) * WW + g * 4;
    const float* xb = x + base;
    float* ob = out + base;

    const float* G = g_gates + batch * 10;
    const float aw  = __ldg(G + 0);
    const float g3h = __ldg(G + 1), g3v = __ldg(G + 2), g3d = __ldg(G + 3);
    const float g2h = __ldg(G + 4), g2v = __ldg(G + 5), g2d = __ldg(G + 6);
    const float g1h = __ldg(G + 7), g1v = __ldg(G + 8), g1d = __ldg(G + 9);

    // ---- forward level 1 (store gated details) ----
    float a1_0[4], a1_1[4];
    float h1_0[4], v1_0[4], d1_0[4];
    float h1_1[4], v1_1[4], d1_1[4];
    #pragma unroll
    for (int ry = 0; ry < 4; ry++) {
        float4 u = *(const float4*)(xb + (size_t)(2 * ry) * WW);
        float4 w = *(const float4*)(xb + (size_t)(2 * ry + 1) * WW);
        float h, v, dd;
        haar_fwd(u.x, u.y, w.x, w.y, a1_0[ry], h, v, dd);
        h1_0[ry] = h * g1h; v1_0[ry] = v * g1v; d1_0[ry] = dd * g1d;
        haar_fwd(u.z, u.w, w.z, w.w, a1_1[ry], h, v, dd);
        h1_1[ry] = h * g1h; v1_1[ry] = v * g1v; d1_1[ry] = dd * g1d;
    }

    // ---- forward level 2 (gated) ----
    float a2[2], h2[2], v2[2], d2[2];
    #pragma unroll
    for (int ry2 = 0; ry2 < 2; ry2++) {
        float h, v, dd;
        haar_fwd(a1_0[2*ry2], a1_1[2*ry2], a1_0[2*ry2+1], a1_1[2*ry2+1],
                 a2[ry2], h, v, dd);
        h2[ry2] = h * g2h; v2[ry2] = v * g2v; d2[ry2] = dd * g2d;
    }

    // ---- level 3: symmetric in both lanes of the pair ----
    float R2[2];
    {
        float pa0 = __shfl_xor_sync(0xFFFFFFFFu, a2[0], 1);
        float pa1 = __shfl_xor_sync(0xFFFFFFFFu, a2[1], 1);
        bool odd = (g & 1);
        float lo0 = odd ? pa0 : a2[0], hi0 = odd ? a2[0] : pa0;
        float lo1 = odd ? pa1 : a2[1], hi1 = odd ? a2[1] : pa1;
        float a, h, v, dd;
        haar_fwd(lo0, hi0, lo1, hi1, a, h, v, dd);
        a *= aw; h *= g3h; v *= g3v; dd *= g3d;
        float x00, x01, x10, x11;
        haar_inv(a, h, v, dd, x00, x01, x10, x11);
        R2[0] = odd ? x01 : x00;   // own L2 column, row 0
        R2[1] = odd ? x11 : x10;   // own L2 column, row 1
    }

    // ---- inverse level 2 ----
    float r1_0[4], r1_1[4];
    #pragma unroll
    for (int ry2 = 0; ry2 < 2; ry2++) {
        haar_inv(R2[ry2], h2[ry2], v2[ry2], d2[ry2],
                 r1_0[2*ry2], r1_1[2*ry2], r1_0[2*ry2+1], r1_1[2*ry2+1]);
    }

    // ---- inverse level 1 + coalesced float4 stores ----
    #pragma unroll
    for (int ry = 0; ry < 4; ry++) {
        float p00, p01, p10, p11, q00, q01, q10, q11;
        haar_inv(r1_0[ry], h1_0[ry], v1_0[ry], d1_0[ry], p00, p01, p10, p11);
        haar_inv(r1_1[ry], h1_1[ry], v1_1[ry], d1_1[ry], q00, q01, q10, q11);
        *(float4*)(ob + (size_t)(2 * ry) * WW)     = make_float4(p00, p01, q00, q01);
        *(float4*)(ob + (size_t)(2 * ry + 1) * WW) = make_float4(p10, p11, q10, q11);
    }
}

// ---------------------------------------------------------------------------
extern "C" void kernel_launch(void* const* d_in, const int* in_sizes, int n_in,
                              void* d_out, int out_size) {
    const float* x   = (const float*)d_in[0];
    const float* Wa  = (const float*)d_in[1];
    const float* ba  = (const float*)d_in[2];
    const float* Wd1 = (const float*)d_in[3];
    const float* bd1 = (const float*)d_in[4];
    const float* Wd2 = (const float*)d_in[5];
    const float* bd2 = (const float*)d_in[6];
    const float* Wd3 = (const float*)d_in[7];
    const float* bd3 = (const float*)d_in[8];
    float* out = (float*)d_out;

    k_zero<<<1, 256>>>();
    k_forward<<<dim3(128, NB), 256>>>(x, Wa, Wd1, Wd2, Wd3);
    k_gates<<<1, 32>>>(ba, bd1, bd2, bd3);
    k_recon<<<dim3(128, NB), 256>>>(x, out);
}

// round 4
// speedup vs baseline: 1.5552x; 1.0809x over previous
#include <cuda_runtime.h>

// WaveletAttention: 3-level Haar DWT -> per-batch scalar gates -> gated IDWT.
// R4: (a) k_forward processes 2 batches/thread -> weight loads amortized 2x,
//     x-load MLP doubled; (b) k_recon uses streaming stores (st.cs) so the
//     write-once output doesn't evict L2-resident x.

#define HH 1024
#define WW 1024
#define NB 16
#define N1c 262144   // 512*512 per component, weights Wd3 (finest)
#define N2c 65536    // 256*256, weights Wd2
#define N3c 16384    // 128*128, weights Wd1 (coarsest)

// per batch (10): [0] approx sigmoid, [1:4] L3 (Wd1), [4:7] L2 (Wd2), [7:10] L1 (Wd3)
__device__ float g_logits[NB * 10];
__device__ float g_gates[NB * 10];

__global__ void k_zero() {
    int i = blockIdx.x * blockDim.x + threadIdx.x;
    if (i < NB * 10) g_logits[i] = 0.0f;
}

__device__ __forceinline__ void haar_fwd(float x00, float x01, float x10, float x11,
                                         float& a, float& h, float& v, float& dd) {
    float s0 = x00 + x01, m0 = x00 - x01;
    float s1 = x10 + x11, m1 = x10 - x11;
    a  = 0.5f * (s0 + s1);
    h  = 0.5f * (s0 - s1);
    v  = 0.5f * (m0 + m1);
    dd = 0.5f * (m0 - m1);
}

__device__ __forceinline__ void haar_inv(float a, float h, float v, float dd,
                                         float& x00, float& x01, float& x10, float& x11) {
    float ph = a + h, mh = a - h;
    float pv = v + dd, mv = v - dd;
    x00 = 0.5f * (ph + pv);
    x01 = 0.5f * (ph - pv);
    x10 = 0.5f * (mh + mv);
    x11 = 0.5f * (mh - mv);
}

// ---------------------------------------------------------------------------
// K1: forward DWT + logit reductions, TWO batches per thread.
// Thread = col-group g (4 cols) x 8 rows; weights loaded once per position.
// grid: (128, NB/2) x 256 threads.
// ---------------------------------------------------------------------------
__global__ void __launch_bounds__(256) k_forward(
    const float* __restrict__ x,
    const float* __restrict__ Wa,
    const float* __restrict__ Wd1,   // [3*N3c, 3] coarsest
    const float* __restrict__ Wd2,   // [3*N2c, 3]
    const float* __restrict__ Wd3)   // [3*N1c, 3] finest
{
    const int b0 = blockIdx.y * 2;           // batches b0, b0+1
    const int bt = blockIdx.x * blockDim.x + threadIdx.x;   // 0..32767
    const int g = bt & 255;        // col group (4 cols), consecutive across lanes
    const int r = bt >> 8;         // row group (8 rows)
    const size_t off = (size_t)(r * 8) * WW + g * 4;
    const float* xA = x + (size_t)b0 * (HH * WW) + off;
    const float* xB = xA + (size_t)(HH * WW);

    float saA = 0.f, s1xA = 0.f, s1yA = 0.f, s1zA = 0.f;
    float s2xA = 0.f, s2yA = 0.f, s2zA = 0.f, s3xA = 0.f, s3yA = 0.f, s3zA = 0.f;
    float saB = 0.f, s1xB = 0.f, s1yB = 0.f, s1zB = 0.f;
    float s2xB = 0.f, s2yB = 0.f, s2zB = 0.f, s3xB = 0.f, s3yB = 0.f, s3zB = 0.f;

    float a0A[4], a1A[4], a0B[4], a1B[4];   // level-1 approx, col pairs 0/1

    // ---- level 1 ----
    #pragma unroll
    for (int ry = 0; ry < 4; ry++) {
        float4 uA = *(const float4*)(xA + (size_t)(2 * ry) * WW);
        float4 wA = *(const float4*)(xA + (size_t)(2 * ry + 1) * WW);
        float4 uB = *(const float4*)(xB + (size_t)(2 * ry) * WW);
        float4 wB = *(const float4*)(xB + (size_t)(2 * ry + 1) * WW);

        const size_t i = (size_t)(r * 4 + ry) * 512 + 2 * g;   // even
        const float* ph = Wd3 + 3 * i;
        const float* pv = Wd3 + 3 * (N1c + i);
        const float* pd = Wd3 + 3 * (2 * (size_t)N1c + i);
        float2 ha = *(const float2*)(ph), hb = *(const float2*)(ph + 2), hc = *(const float2*)(ph + 4);
        float2 va = *(const float2*)(pv), vb = *(const float2*)(pv + 2), vc = *(const float2*)(pv + 4);
        float2 da = *(const float2*)(pd), db = *(const float2*)(pd + 2), dc = *(const float2*)(pd + 4);

        float h0, v0, d0, h1, v1, d1;
        haar_fwd(uA.x, uA.y, wA.x, wA.y, a0A[ry], h0, v0, d0);
        haar_fwd(uA.z, uA.w, wA.z, wA.w, a1A[ry], h1, v1, d1);
        s1xA += h0 * ha.x + h1 * hb.y + v0 * va.x + v1 * vb.y + d0 * da.x + d1 * db.y;
        s1yA += h0 * ha.y + h1 * hc.x + v0 * va.y + v1 * vc.x + d0 * da.y + d1 * dc.x;
        s1zA += h0 * hb.x + h1 * hc.y + v0 * vb.x + v1 * vc.y + d0 * db.x + d1 * dc.y;

        haar_fwd(uB.x, uB.y, wB.x, wB.y, a0B[ry], h0, v0, d0);
        haar_fwd(uB.z, uB.w, wB.z, wB.w, a1B[ry], h1, v1, d1);
        s1xB += h0 * ha.x + h1 * hb.y + v0 * va.x + v1 * vb.y + d0 * da.x + d1 * db.y;
        s1yB += h0 * ha.y + h1 * hc.x + v0 * va.y + v1 * vc.x + d0 * da.y + d1 * dc.x;
        s1zB += h0 * hb.x + h1 * hc.y + v0 * vb.x + v1 * vc.y + d0 * db.x + d1 * dc.y;
    }

    // ---- level 2 ----
    float a2A[2], a2B[2];
    #pragma unroll
    for (int ry2 = 0; ry2 < 2; ry2++) {
        const size_t i = (size_t)(r * 2 + ry2) * 256 + g;
        const float* ph = Wd2 + 3 * i;
        const float* pv = Wd2 + 3 * (N2c + i);
        const float* pd = Wd2 + 3 * (2 * (size_t)N2c + i);
        float w0 = __ldg(ph + 0), w1 = __ldg(ph + 1), w2 = __ldg(ph + 2);
        float w3 = __ldg(pv + 0), w4 = __ldg(pv + 1), w5 = __ldg(pv + 2);
        float w6 = __ldg(pd + 0), w7 = __ldg(pd + 1), w8 = __ldg(pd + 2);

        float h, v, dd;
        haar_fwd(a0A[2*ry2], a1A[2*ry2], a0A[2*ry2+1], a1A[2*ry2+1], a2A[ry2], h, v, dd);
        s2xA += h * w0 + v * w3 + dd * w6;
        s2yA += h * w1 + v * w4 + dd * w7;
        s2zA += h * w2 + v * w5 + dd * w8;

        haar_fwd(a0B[2*ry2], a1B[2*ry2], a0B[2*ry2+1], a1B[2*ry2+1], a2B[ry2], h, v, dd);
        s2xB += h * w0 + v * w3 + dd * w6;
        s2yB += h * w1 + v * w4 + dd * w7;
        s2zB += h * w2 + v * w5 + dd * w8;
    }

    // ---- level 3: combine lane pairs; only even lane accumulates ----
    {
        float pA0 = __shfl_xor_sync(0xFFFFFFFFu, a2A[0], 1);
        float pA1 = __shfl_xor_sync(0xFFFFFFFFu, a2A[1], 1);
        float pB0 = __shfl_xor_sync(0xFFFFFFFFu, a2B[0], 1);
        float pB1 = __shfl_xor_sync(0xFFFFFFFFu, a2B[1], 1);
        if ((g & 1) == 0) {
            const size_t i = (size_t)r * 128 + (g >> 1);
            const float* ph = Wd1 + 3 * i;
            const float* pv = Wd1 + 3 * (N3c + i);
            const float* pd = Wd1 + 3 * (2 * (size_t)N3c + i);
            float w0 = __ldg(ph + 0), w1 = __ldg(ph + 1), w2 = __ldg(ph + 2);
            float w3 = __ldg(pv + 0), w4 = __ldg(pv + 1), w5 = __ldg(pv + 2);
            float w6 = __ldg(pd + 0), w7 = __ldg(pd + 1), w8 = __ldg(pd + 2);
            float wa = __ldg(Wa + i);

            float a, h, v, dd;
            haar_fwd(a2A[0], pA0, a2A[1], pA1, a, h, v, dd);
            s3xA = h * w0 + v * w3 + dd * w6;
            s3yA = h * w1 + v * w4 + dd * w7;
            s3zA = h * w2 + v * w5 + dd * w8;
            saA  = a * wa;

            haar_fwd(a2B[0], pB0, a2B[1], pB1, a, h, v, dd);
            s3xB = h * w0 + v * w3 + dd * w6;
            s3yB = h * w1 + v * w4 + dd * w7;
            s3zB = h * w2 + v * w5 + dd * w8;
            saB  = a * wa;
        }
    }

    // ---- block reduction of 20 scalars ----
    float vals[20] = {saA, s3xA, s3yA, s3zA, s2xA, s2yA, s2zA, s1xA, s1yA, s1zA,
                      saB, s3xB, s3yB, s3zB, s2xB, s2yB, s2zB, s1xB, s1yB, s1zB};
    __shared__ float sm[20][8];
    int lane = threadIdx.x & 31;
    int wid  = threadIdx.x >> 5;
    #pragma unroll
    for (int k = 0; k < 20; k++) {
        float v = vals[k];
        #pragma unroll
        for (int off2 = 16; off2 > 0; off2 >>= 1)
            v += __shfl_down_sync(0xFFFFFFFFu, v, off2);
        if (lane == 0) sm[k][wid] = v;
    }
    __syncthreads();
    if (threadIdx.x < 20) {
        float t = 0.f;
        #pragma unroll
        for (int w = 0; w < 8; w++) t += sm[threadIdx.x][w];
        int b = b0 + (threadIdx.x >= 10 ? 1 : 0);
        atomicAdd(&g_logits[b * 10 + (threadIdx.x % 10)], t);
    }
}

// ---------------------------------------------------------------------------
// K2: per-batch gates (tiny)
// ---------------------------------------------------------------------------
__device__ __forceinline__ void softmax3(const float* l, const float* bd, float* g) {
    float l0 = l[0] + bd[0], l1 = l[1] + bd[1], l2 = l[2] + bd[2];
    float m = fmaxf(fmaxf(l0, l1), l2);
    float e0 = __expf(l0 - m), e1 = __expf(l1 - m), e2 = __expf(l2 - m);
    float inv = 1.0f / (e0 + e1 + e2);
    g[0] = e0 * inv; g[1] = e1 * inv; g[2] = e2 * inv;
}

__global__ void k_gates(const float* __restrict__ ba,
                        const float* __restrict__ bd1,
                        const float* __restrict__ bd2,
                        const float* __restrict__ bd3)
{
    int b = threadIdx.x;
    if (b >= NB) return;
    const float* L = g_logits + b * 10;
    float* G = g_gates + b * 10;
    G[0] = 1.0f / (1.0f + __expf(-(L[0] + ba[0])));
    softmax3(L + 1, bd1, G + 1);
    softmax3(L + 4, bd2, G + 4);
    softmax3(L + 7, bd3, G + 7);
}

// ---------------------------------------------------------------------------
// K3: single-pass reconstruct; streaming stores keep x L2-resident.
// ---------------------------------------------------------------------------
__device__ __forceinline__ void stcs4(float* p, float a, float b, float c, float d) {
    float4 v = make_float4(a, b, c, d);
    asm volatile("st.global.cs.v4.f32 [%0], {%1, %2, %3, %4};"
                 :: "l"(p), "f"(v.x), "f"(v.y), "f"(v.z), "f"(v.w) : "memory");
}

__global__ void __launch_bounds__(256) k_recon(
    const float* __restrict__ x, float* __restrict__ out)
{
    const int batch = blockIdx.y;
    const int bt = blockIdx.x * blockDim.x + threadIdx.x;
    const int g = bt & 255;
    const int r = bt >> 8;
    const size_t base = (size_t)batch * (HH * WW) + (size_t)(r * 8) * WW + g * 4;
    const float* xb = x + base;
    float* ob = out + base;

    const float* G = g_gates + batch * 10;
    const float aw  = __ldg(G + 0);
    const float g3h = __ldg(G + 1), g3v = __ldg(G + 2), g3d = __ldg(G + 3);
    const float g2h = __ldg(G + 4), g2v = __ldg(G + 5), g2d = __ldg(G + 6);
    const float g1h = __ldg(G + 7), g1v = __ldg(G + 8), g1d = __ldg(G + 9);

    // ---- forward level 1 (store gated details) ----
    float a1_0[4], a1_1[4];
    float h1_0[4], v1_0[4], d1_0[4];
    float h1_1[4], v1_1[4], d1_1[4];
    #pragma unroll
    for (int ry = 0; ry < 4; ry++) {
        float4 u = *(const float4*)(xb + (size_t)(2 * ry) * WW);
        float4 w = *(const float4*)(xb + (size_t)(2 * ry + 1) * WW);
        float h, v, dd;
        haar_fwd(u.x, u.y, w.x, w.y, a1_0[ry], h, v, dd);
        h1_0[ry] = h * g1h; v1_0[ry] = v * g1v; d1_0[ry] = dd * g1d;
        haar_fwd(u.z, u.w, w.z, w.w, a1_1[ry], h, v, dd);
        h1_1[ry] = h * g1h; v1_1[ry] = v * g1v; d1_1[ry] = dd * g1d;
    }

    // ---- forward level 2 (gated) ----
    float a2[2], h2[2], v2[2], d2[2];
    #pragma unroll
    for (int ry2 = 0; ry2 < 2; ry2++) {
        float h, v, dd;
        haar_fwd(a1_0[2*ry2], a1_1[2*ry2], a1_0[2*ry2+1], a1_1[2*ry2+1],
                 a2[ry2], h, v, dd);
        h2[ry2] = h * g2h; v2[ry2] = v * g2v; d2[ry2] = dd * g2d;
    }

    // ---- level 3: symmetric in both lanes of the pair ----
    float R2[2];
    {
        float pa0 = __shfl_xor_sync(0xFFFFFFFFu, a2[0], 1);
        float pa1 = __shfl_xor_sync(0xFFFFFFFFu, a2[1], 1);
        bool odd = (g & 1);
        float lo0 = odd ? pa0 : a2[0], hi0 = odd ? a2[0] : pa0;
        float lo1 = odd ? pa1 : a2[1], hi1 = odd ? a2[1] : pa1;
        float a, h, v, dd;
        haar_fwd(lo0, hi0, lo1, hi1, a, h, v, dd);
        a *= aw; h *= g3h; v *= g3v; dd *= g3d;
        float x00, x01, x10, x11;
        haar_inv(a, h, v, dd, x00, x01, x10, x11);
        R2[0] = odd ? x01 : x00;
        R2[1] = odd ? x11 : x10;
    }

    // ---- inverse level 2 ----
    float r1_0[4], r1_1[4];
    #pragma unroll
    for (int ry2 = 0; ry2 < 2; ry2++) {
        haar_inv(R2[ry2], h2[ry2], v2[ry2], d2[ry2],
                 r1_0[2*ry2], r1_1[2*ry2], r1_0[2*ry2+1], r1_1[2*ry2+1]);
    }

    // ---- inverse level 1 + streaming float4 stores ----
    #pragma unroll
    for (int ry = 0; ry < 4; ry++) {
        float p00, p01, p10, p11, q00, q01, q10, q11;
        haar_inv(r1_0[ry], h1_0[ry], v1_0[ry], d1_0[ry], p00, p01, p10, p11);
        haar_inv(r1_1[ry], h1_1[ry], v1_1[ry], d1_1[ry], q00, q01, q10, q11);
        stcs4(ob + (size_t)(2 * ry) * WW,     p00, p01, q00, q01);
        stcs4(ob + (size_t)(2 * ry + 1) * WW, p10, p11, q10, q11);
    }
}

// ---------------------------------------------------------------------------
extern "C" void kernel_launch(void* const* d_in, const int* in_sizes, int n_in,
                              void* d_out, int out_size) {
    const float* x   = (const float*)d_in[0];
    const float* Wa  = (const float*)d_in[1];
    const float* ba  = (const float*)d_in[2];
    const float* Wd1 = (const float*)d_in[3];
    const float* bd1 = (const float*)d_in[4];
    const float* Wd2 = (const float*)d_in[5];
    const float* bd2 = (const float*)d_in[6];
    const float* Wd3 = (const float*)d_in[7];
    const float* bd3 = (const float*)d_in[8];
    float* out = (float*)d_out;

    k_zero<<<1, 256>>>();
    k_forward<<<dim3(128, NB / 2), 256>>>(x, Wa, Wd1, Wd2, Wd3);
    k_gates<<<1, 32>>>(ba, bd1, bd2, bd3);
    k_recon<<<dim3(128, NB), 256>>>(x, out);
}